// round 16
// baseline (speedup 1.0000x reference)
#include <cuda_runtime.h>
#include <cuda_fp16.h>
#include <cstdint>

#define NN 4096
#define BB 64
#define CC 64
#define EE 16
#define G  2            // batches per block (block N = 128)
#define KC 64           // K per chunk

// ---- arch-specific gate: tcgen05 only in the sm_103a/f pass ----
#if defined(__CUDA_ARCH__) && (__CUDA_ARCH__ == 1030) && \
    (defined(__CUDA_ARCH_SPECIFIC__) || defined(__CUDA_ARCH_FAMILY_SPECIFIC__))
#define USE_TC 1
#else
#define USE_TC 0
#endif

// ---- mma.sync fallback smem layout: pitch 144B per 64-fp16 row ----
#define PKB   144
#define ASZ   18432u          // A region 128*144
#define BGS   9216u           // per-batch B region 64*144
#define STAGE 36864u          // A + 2*B
#define NSTG  3
#define SMEM_TOTAL (3 * 36864)

// ---- tcgen05 smem layout: SW128, 128B rows, stages 1024-aligned ----
#define TCA   16384u          // A region: 128 rows * 128B
#define TCB   8192u           // per-batch B region: 64 rows * 128B
#define TCSTAGE 32768u        // A + 2*B
#define SWZ(o) ((o) ^ (((o) >> 3) & 0x70))
// idesc kind::f16: dtype F32(1<<4), a=f16(0), b=f16(0), N=64(8<<17), M=128(8<<24)
#define TC_IDESC 0x8100010u

// ---- device buffers (fp16) ----
__device__ __align__(16) __half g_Sh[(size_t)NN * NN];
__device__ __align__(16) __half g_Xh[(size_t)BB * NN * CC];
__device__ __align__(16) __half g_B1T[(size_t)BB * CC * NN];
__device__ __align__(16) __half g_B2T[(size_t)BB * CC * NN];
__device__ __align__(16) __half g_W2T[CC * CC], g_W1T[CC * CC], g_WdT[CC * CC];

__device__ __forceinline__ uint32_t smem_u32(const void* p) {
    uint32_t a;
    asm("{ .reg .u64 t; cvta.to.shared.u64 t, %1; cvt.u32.u64 %0, t; }" : "=r"(a) : "l"(p));
    return a;
}
#define CPA(dst, src) \
    asm volatile("cp.async.cg.shared.global [%0], [%1], 16;" :: "r"(dst), "l"(src) : "memory")
#define CP_COMMIT() asm volatile("cp.async.commit_group;" ::: "memory")
#define CP_WAIT0()  asm volatile("cp.async.wait_group 0;" ::: "memory")
#define CP_WAIT1()  asm volatile("cp.async.wait_group 1;" ::: "memory")

#if USE_TC
// ================= tcgen05 helpers (sm_103a pass only) =================
__device__ __forceinline__ bool elect1() {
    uint32_t r;
    asm volatile("{\n\t.reg .pred p;\n\telect.sync _|p, 0xFFFFFFFF;\n\tselp.b32 %0,1,0,p;\n\t}" : "=r"(r));
    return r != 0;
}
__device__ __forceinline__ uint64_t sdesc(uint32_t addr) {
    // SW128 (layout=2), version=1 (Blackwell), SBO=64, LBO=1
    return 0x4000404000010000ULL | (uint64_t)((addr >> 4) & 0x3FFF);
}
__device__ __forceinline__ void mma_f16_ss(uint32_t d, uint64_t a, uint64_t b, uint32_t en) {
    asm volatile(
        "{\n\t.reg .pred p;\n\tsetp.ne.u32 p, %4, 0;\n\t"
        "tcgen05.mma.cta_group::1.kind::f16 [%0], %1, %2, %3, {%5,%5,%5,%5}, p;\n\t}"
        :: "r"(d), "l"(a), "l"(b), "r"(TC_IDESC), "r"(en), "r"(0u) : "memory");
}
#define TC_COMMIT(mbar) \
    asm volatile("tcgen05.commit.cta_group::1.mbarrier::arrive::one.shared::cluster.b64 [%0];" :: "r"(mbar) : "memory")
#define MBAR_INIT(a) \
    asm volatile("mbarrier.init.shared.b64 [%0], %1;" :: "r"(a), "r"(1u) : "memory")
#define MBAR_INVAL(a) \
    asm volatile("mbarrier.inval.shared.b64 [%0];" :: "r"(a) : "memory")
__device__ __forceinline__ void mbar_wait(uint32_t mbar, uint32_t parity) {
    asm volatile(
        "{\n\t.reg .pred P;\n\tWL_%=:\n\t"
        "mbarrier.try_wait.parity.acquire.cta.shared::cta.b64 P, [%0], %1, 0x989680;\n\t"
        "@P bra.uni WD_%=;\n\tbra.uni WL_%=;\n\tWD_%=:\n\t}"
        :: "r"(mbar), "r"(parity) : "memory");
}
#define TC_ALLOC(sa) \
    asm volatile("tcgen05.alloc.cta_group::1.sync.aligned.shared::cta.b32 [%0], %1;" :: "r"(sa), "r"(128u) : "memory")
#define TC_DEALLOC(tm) \
    asm volatile("tcgen05.dealloc.cta_group::1.sync.aligned.b32 %0, %1;" :: "r"(tm), "r"(128u))
#define TC_FENCE_AFTER()  asm volatile("tcgen05.fence::after_thread_sync;" ::: "memory")
#define TC_WAIT_LD()      asm volatile("tcgen05.wait::ld.sync.aligned;" ::: "memory")
#define FENCE_PROXY()     asm volatile("fence.proxy.async.shared::cta;" ::: "memory")
#define LDTM32(r, a) \
    asm volatile( \
        "tcgen05.ld.sync.aligned.32x32b.x32.b32 " \
        "{%0, %1, %2, %3, %4, %5, %6, %7, " \
        " %8, %9, %10, %11, %12, %13, %14, %15, " \
        " %16, %17, %18, %19, %20, %21, %22, %23, " \
        " %24, %25, %26, %27, %28, %29, %30, %31}, [%32];" \
        : "=r"((r)[0]),  "=r"((r)[1]),  "=r"((r)[2]),  "=r"((r)[3]), \
          "=r"((r)[4]),  "=r"((r)[5]),  "=r"((r)[6]),  "=r"((r)[7]), \
          "=r"((r)[8]),  "=r"((r)[9]),  "=r"((r)[10]), "=r"((r)[11]), \
          "=r"((r)[12]), "=r"((r)[13]), "=r"((r)[14]), "=r"((r)[15]), \
          "=r"((r)[16]), "=r"((r)[17]), "=r"((r)[18]), "=r"((r)[19]), \
          "=r"((r)[20]), "=r"((r)[21]), "=r"((r)[22]), "=r"((r)[23]), \
          "=r"((r)[24]), "=r"((r)[25]), "=r"((r)[26]), "=r"((r)[27]), \
          "=r"((r)[28]), "=r"((r)[29]), "=r"((r)[30]), "=r"((r)[31]) \
        : "r"(a))
#else
// ================= mma.sync helpers (plain sm_103 pass) =================
__device__ __forceinline__ void ldsm4(uint32_t* r, uint32_t addr) {
    asm volatile("ldmatrix.sync.aligned.m8n8.x4.shared.b16 {%0,%1,%2,%3}, [%4];"
        : "=r"(r[0]), "=r"(r[1]), "=r"(r[2]), "=r"(r[3]) : "r"(addr));
}
__device__ __forceinline__ void mma16816(float* c, const uint32_t* a, const uint32_t* b) {
    asm volatile("mma.sync.aligned.m16n8k16.row.col.f32.f16.f16.f32 "
        "{%0,%1,%2,%3}, {%4,%5,%6,%7}, {%8,%9}, {%0,%1,%2,%3};"
        : "+f"(c[0]), "+f"(c[1]), "+f"(c[2]), "+f"(c[3])
        : "r"(a[0]), "r"(a[1]), "r"(a[2]), "r"(a[3]), "r"(b[0]), "r"(b[1]));
}
#endif

// ---------------------------------------------------------------------------
__global__ __launch_bounds__(256) void supports_kernel(
    const float* __restrict__ adj, const float* __restrict__ emb)
{
    __shared__ float row[NN];
    __shared__ float red[8];
    const int n = blockIdx.x, tid = threadIdx.x;
    const int lane = tid & 31, wid = tid >> 5;

    float a[EE];
#pragma unroll
    for (int e = 0; e < EE; e++) a[e] = adj[n * EE + e];

    float mx = 0.0f;
#pragma unroll
    for (int j = 0; j < NN; j += 256) {
        int m = j + tid;
        float v = 0.0f;
#pragma unroll
        for (int e = 0; e < EE; e++) v = fmaf(a[e], emb[e * NN + m], v);
        v = fmaxf(v, 0.0f);
        row[m] = v;
        mx = fmaxf(mx, v);
    }
#pragma unroll
    for (int o = 16; o > 0; o >>= 1) mx = fmaxf(mx, __shfl_xor_sync(0xffffffffu, mx, o));
    if (lane == 0) red[wid] = mx;
    __syncthreads();
    mx = red[0];
#pragma unroll
    for (int w = 1; w < 8; w++) mx = fmaxf(mx, red[w]);
    __syncthreads();

    float s = 0.0f;
#pragma unroll
    for (int j = 0; j < NN; j += 256) {
        int m = j + tid;
        float e = __expf(row[m] - mx);
        row[m] = e;
        s += e;
    }
#pragma unroll
    for (int o = 16; o > 0; o >>= 1) s += __shfl_xor_sync(0xffffffffu, s, o);
    if (lane == 0) red[wid] = s;
    __syncthreads();
    s = 0.0f;
#pragma unroll
    for (int w = 0; w < 8; w++) s += red[w];
    const float inv = 1.0f / s;
#pragma unroll
    for (int j = 0; j < NN; j += 256) {
        int m = j + tid;
        g_Sh[(size_t)n * NN + m] = __float2half_rn(row[m] * inv);
    }
}

__global__ __launch_bounds__(256) void prep_x(const float* __restrict__ x)
{
    size_t i = (size_t)blockIdx.x * blockDim.x + threadIdx.x;  // float4 index
    float4 v = ((const float4*)x)[i];
    __half2* ph = (__half2*)g_Xh;
    ph[2 * i]     = __half2{__float2half_rn(v.x), __float2half_rn(v.y)};
    ph[2 * i + 1] = __half2{__float2half_rn(v.z), __float2half_rn(v.w)};
}

__global__ void prep_w(const float* __restrict__ W)
{
#pragma unroll
    for (int q = 0; q < 16; q++) {
        int idx = threadIdx.x + q * 256;
        int i = idx >> 6, o = idx & 63;
        int t = o * CC + i;                     // transposed [o][i]
        float w0 = W[i * CC + o];
        float w1 = W[CC * CC + i * CC + o] * 0.5f;
        float w2 = W[2 * CC * CC + i * CC + o];
        g_W2T[t] = __float2half_rn(w2);
        g_W1T[t] = __float2half_rn(w1);
        g_WdT[t] = __float2half_rn(w0 - w2);
    }
}

// ---------------------------------------------------------------------------
// Unified GEMM: D[128 x (2x64)] = sum_k S @ BopT^T (+ X@W epi chunk).
// mode 0: (epi only) B1T = (X@W2)^T;  mode 1: B2T = (2(S@B1)+X@W1)^T;
// mode 2: out = S@B2 + X@(W0-W2) + bias.
// Body: tcgen05 in the sm_103a pass, mma.sync otherwise. Same launch config.
// ---------------------------------------------------------------------------
__global__ __launch_bounds__(256, 2) __cluster_dims__(1, 1, 1)
void cheb_gemm(const float* __restrict__ bias, float* __restrict__ out, int mode)
{
    extern __shared__ char smem[];
    const uint32_t sb = smem_u32(smem);
    const int tid = threadIdx.x, wid = tid >> 5, lane = tid & 31;
    const int b0 = blockIdx.x * G;
    const int n0 = blockIdx.y * 128;

    const __half* Bop = (mode == 1) ? g_B1T : g_B2T;
    const __half* WT  = (mode == 0) ? g_W2T : (mode == 1) ? g_W1T : g_WdT;
    const int nMain = (mode == 0) ? 0 : (NN / KC);

#if USE_TC
    // =================== tcgen05 path ===================
    // alloc FIRST (warp 4 only, no relinquish anywhere), then barrier.
    if (wid == 4) TC_ALLOC(sb + 0);
    __syncthreads();
    if (tid == 0) { MBAR_INIT(sb + 8); MBAR_INIT(sb + 16); }
    __syncthreads();
    uint32_t tmem;
    asm volatile("ld.shared.b32 %0, [%1];" : "=r"(tmem) : "r"(sb + 0));

    // 1024-aligned staging base (SW128 swizzle correctness)
    const uint32_t st0 = (sb + 32u + 1023u) & ~1023u;
    auto stageA = [&](int st) { return st0 + (uint32_t)st * TCSTAGE; };

    auto load_main = [&](int cc) {
        const uint32_t stA = stageA(cc & 1);
        const int k0 = cc * KC;
#pragma unroll
        for (int q = 0; q < 4; q++) {           // A: 1024 16B ops (S rows, SW128)
            int p = tid + 256 * q;
            int r = p >> 3, j = p & 7;
            const __half* s = g_Sh + (size_t)(n0 + r) * NN + k0 + j * 8;
            CPA(stA + SWZ((uint32_t)(r * 128 + j * 16)), s);
        }
#pragma unroll
        for (int q = 0; q < 4; q++) {           // B: 1024 16B ops
            int p = tid + 256 * q;
            int g = p >> 9, r = (p >> 3) & 63, j = p & 7;
            const __half* s = Bop + ((size_t)((b0 + g) * CC + r)) * NN + k0 + j * 8;
            CPA(stA + TCA + (uint32_t)g * TCB + SWZ((uint32_t)(r * 128 + j * 16)), s);
        }
    };

    auto issue_mma = [&](int cc, int first) {
        const uint32_t stA = stageA(cc & 1);
        uint64_t ad = sdesc(stA);
#pragma unroll
        for (int g = 0; g < G; g++) {
            uint64_t bd = sdesc(stA + TCA + (uint32_t)g * TCB);
            uint32_t D = tmem + g * 64;
#pragma unroll
            for (int ks = 0; ks < 4; ks++)
                mma_f16_ss(D, ad + ks * 2, bd + ks * 2, (first && ks == 0) ? 0u : 1u);
        }
        TC_COMMIT(sb + 8 + (uint32_t)(cc & 1) * 8);
    };

    if (nMain > 0) {
        load_main(0);
        CP_COMMIT(); CP_WAIT0(); FENCE_PROXY();
        __syncthreads();
        for (int c = 0; c < nMain; c++) {
            if (wid == 4 && elect1()) issue_mma(c, c == 0);
            if (c + 1 < nMain) {
                if (c >= 1) mbar_wait(sb + 8 + (uint32_t)((c - 1) & 1) * 8, ((c - 1) >> 1) & 1);
                load_main(c + 1);
                CP_COMMIT(); CP_WAIT0(); FENCE_PROXY();
            }
            __syncthreads();
        }
        // drain both in-flight chunks before stage reuse
        if (nMain >= 2) mbar_wait(sb + 8 + (uint32_t)((nMain - 2) & 1) * 8, ((nMain - 2) >> 1) & 1);
        mbar_wait(sb + 8 + (uint32_t)((nMain - 1) & 1) * 8, ((nMain - 1) >> 1) & 1);
        __syncthreads();
    }

    // ---- epi chunk: X[b0+g] @ W  (A per-g in stage g, W in stage0 B) ----
    {
#pragma unroll
        for (int q = 0; q < 8; q++) {           // X: 2048 ops
            int p = tid + 256 * q;
            int g = p >> 10, r = (p >> 3) & 127, j = p & 7;
            const __half* s = g_Xh + ((size_t)(b0 + g) * NN + n0 + r) * CC + j * 8;
            CPA(stageA(g) + SWZ((uint32_t)(r * 128 + j * 16)), s);
        }
#pragma unroll
        for (int q = 0; q < 2; q++) {           // W: 512 ops
            int p = tid + 256 * q;
            int r = p >> 3, j = p & 7;
            const __half* s = WT + r * CC + j * 8;
            CPA(stageA(0) + TCA + SWZ((uint32_t)(r * 128 + j * 16)), s);
        }
        CP_COMMIT(); CP_WAIT0(); FENCE_PROXY();
        __syncthreads();
        if (wid == 4 && elect1()) {
            uint64_t bd = sdesc(stageA(0) + TCA);
#pragma unroll
            for (int g = 0; g < G; g++) {
                uint64_t ad = sdesc(stageA(g));
                uint32_t D = tmem + g * 64;
#pragma unroll
                for (int ks = 0; ks < 4; ks++)
                    mma_f16_ss(D, ad + ks * 2, bd + ks * 2,
                               (nMain == 0 && ks == 0) ? 0u : 1u);
            }
            TC_COMMIT(sb + 8 + (uint32_t)(nMain & 1) * 8);
        }
        __syncthreads();
        mbar_wait(sb + 8 + (uint32_t)(nMain & 1) * 8, (nMain >> 1) & 1);
        TC_FENCE_AFTER();
    }

    // ---- epilogue: warps 0-3 read TMEM ----
    if (wid < 4) {
        const int n = n0 + wid * 32 + lane;
#pragma unroll 1
        for (int g = 0; g < G; g++) {
            const int b = b0 + g;
            uint32_t r[64];
            LDTM32(r, tmem + g * 64);
            LDTM32(r + 32, tmem + g * 64 + 32);
            TC_WAIT_LD();
            if (mode == 2) {
#pragma unroll
                for (int cc = 0; cc < 64; cc++)
                    out[((size_t)b * NN + n) * CC + cc] = __uint_as_float(r[cc]) + __ldg(bias + cc);
            } else {
                __half* dh = (mode == 0) ? g_B1T : g_B2T;
                const float sc = (mode == 1) ? 2.0f : 1.0f;
#pragma unroll
                for (int cc = 0; cc < 64; cc++)
                    dh[(size_t)(b * CC + cc) * NN + n] = __float2half_rn(__uint_as_float(r[cc]) * sc);
            }
        }
    }
    __syncthreads();
    if (tid == 0) { MBAR_INVAL(sb + 8); MBAR_INVAL(sb + 16); }
    __syncthreads();
    if (wid == 4) TC_DEALLOC(tmem);

#else
    // =================== mma.sync fallback (proven R6 body) ===================
    const int wm = wid >> 1, wn = wid & 1;
    const int m0 = wm * 32;

    float acc[2][8][4];
#pragma unroll
    for (int a = 0; a < 2; a++)
#pragma unroll
        for (int b = 0; b < 8; b++)
#pragma unroll
            for (int c = 0; c < 4; c++) acc[a][b][c] = 0.0f;

    const uint32_t aRowOff = (uint32_t)(lane & 15) * PKB + ((lane >> 4) & 1) * 16;
    const uint32_t bRowOff = (uint32_t)((lane & 7) + ((lane >> 4) & 1) * 8) * PKB
                           + ((lane >> 3) & 1) * 16;

    auto load_main = [&](int cc) {
        const uint32_t st = sb + (uint32_t)(cc % NSTG) * STAGE;
        const int k0 = cc * KC;
#pragma unroll
        for (int q = 0; q < 4; q++) {
            int p = tid + 256 * q;
            int r = p >> 3, j = p & 7;
            const __half* s = g_Sh + (size_t)(n0 + r) * NN + k0 + j * 8;
            CPA(st + (uint32_t)r * PKB + j * 16, s);
        }
#pragma unroll
        for (int q = 0; q < 4; q++) {
            int p = tid + 256 * q;
            int g = p >> 9, r = (p >> 3) & 63, j = p & 7;
            const __half* s = Bop + ((size_t)((b0 + g) * CC + r)) * NN + k0 + j * 8;
            CPA(st + ASZ + (uint32_t)g * BGS + (uint32_t)r * PKB + j * 16, s);
        }
    };

    auto load_epi = [&]() {
#pragma unroll
        for (int q = 0; q < 8; q++) {
            int p = tid + 256 * q;
            int g = p >> 10, r = (p >> 3) & 127, j = p & 7;
            const __half* s = g_Xh + ((size_t)(b0 + g) * NN + n0 + r) * CC + j * 8;
            CPA(sb + (uint32_t)g * STAGE + (uint32_t)r * PKB + j * 16, s);
        }
#pragma unroll
        for (int q = 0; q < 2; q++) {
            int p = tid + 256 * q;
            int r = p >> 3, j = p & 7;
            const __half* s = WT + r * CC + j * 8;
            CPA(sb + 2u * STAGE + (uint32_t)r * PKB + j * 16, s);
        }
    };

    auto do_chunk = [&](uint32_t aBase, uint32_t bBase) {
#pragma unroll
        for (int kk = 0; kk < 4; kk++) {
            uint32_t a[2][4];
#pragma unroll
            for (int mt = 0; mt < 2; mt++)
                ldsm4(a[mt], aBase + (uint32_t)(m0 + mt * 16) * PKB + kk * 32 + aRowOff);
#pragma unroll
            for (int ntp = 0; ntp < 4; ntp++) {
                uint32_t b[4];
                ldsm4(b, bBase + (uint32_t)(ntp * 16) * PKB + kk * 32 + bRowOff);
#pragma unroll
                for (int mt = 0; mt < 2; mt++)
#pragma unroll
                    for (int h = 0; h < 2; h++)
                        mma16816(acc[mt][ntp * 2 + h], a[mt], b + 2 * h);
            }
        }
    };

    if (nMain > 0) {
        load_main(0); CP_COMMIT();
        load_main(1); CP_COMMIT();
        for (int c = 0; c < nMain; c++) {
            if (c + 2 <= nMain) CP_WAIT1(); else CP_WAIT0();
            __syncthreads();
            if (c + 2 < nMain) { load_main(c + 2); CP_COMMIT(); }
            const uint32_t st = sb + (uint32_t)(c % NSTG) * STAGE;
            do_chunk(st, st + ASZ + (uint32_t)wn * BGS);
        }
        __syncthreads();
    }

    load_epi();
    CP_COMMIT(); CP_WAIT0();
    __syncthreads();
    do_chunk(sb + (uint32_t)wn * STAGE, sb + 2u * STAGE);

    const int g = wn;
    const int rA = lane >> 2;
    const int c0 = (lane & 3) * 2;
    if (mode == 2) {
#pragma unroll
        for (int mt = 0; mt < 2; mt++) {
            int m = n0 + m0 + mt * 16 + rA;
#pragma unroll
            for (int nt = 0; nt < 8; nt++) {
                int col = nt * 8 + c0;
                float b0v = __ldg(bias + col), b1v = __ldg(bias + col + 1);
                size_t base = ((size_t)(b0 + g) * NN + m) * CC + col;
                *(float2*)(out + base) = make_float2(acc[mt][nt][0] + b0v, acc[mt][nt][1] + b1v);
                *(float2*)(out + base + 8 * CC) = make_float2(acc[mt][nt][2] + b0v, acc[mt][nt][3] + b1v);
            }
        }
    } else {
        __half* dh = (mode == 0) ? g_B1T : g_B2T;
        const float sc = (mode == 1) ? 2.0f : 1.0f;
#pragma unroll
        for (int mt = 0; mt < 2; mt++) {
            int m = n0 + m0 + mt * 16 + rA;
#pragma unroll
            for (int nt = 0; nt < 8; nt++) {
                int col = nt * 8 + c0;
#pragma unroll
                for (int q = 0; q < 4; q++) {
                    float v = acc[mt][nt][q] * sc;
                    size_t o = ((size_t)((b0 + g) * CC + col + (q & 1))) * NN + m + (q >> 1) * 8;
                    dh[o] = __float2half_rn(v);
                }
            }
        }
    }
#endif
}

// ---------------------------------------------------------------------------
extern "C" void kernel_launch(void* const* d_in, const int* in_sizes, int n_in,
                              void* d_out, int out_size)
{
    const float* x    = (const float*)d_in[0];  // [64, 4096, 64]
    const float* adj  = (const float*)d_in[1];  // [4096, 16]
    const float* emb  = (const float*)d_in[2];  // [16, 4096]
    const float* W    = (const float*)d_in[3];  // [3, 64, 64]
    const float* bias = (const float*)d_in[4];  // [64]
    float* out = (float*)d_out;                 // [64, 4096, 64]
    (void)in_sizes; (void)n_in; (void)out_size;

    cudaFuncSetAttribute(cheb_gemm, cudaFuncAttributeMaxDynamicSharedMemorySize, SMEM_TOTAL);

    supports_kernel<<<NN, 256>>>(adj, emb);
    prep_x<<<(BB * NN * CC / 4) / 256, 256>>>(x);
    prep_w<<<1, 256>>>(W);

    dim3 grid(BB / G, NN / 128);
    cheb_gemm<<<grid, 256, SMEM_TOTAL>>>(bias, out, 0);  // B1 = X@W2
    cheb_gemm<<<grid, 256, SMEM_TOTAL>>>(bias, out, 1);  // B2 = 2(S@B1) + X@W1
    cheb_gemm<<<grid, 256, SMEM_TOTAL>>>(bias, out, 2);  // out = S@B2 + X@(W0-W2) + bias
}

// round 17
// speedup vs baseline: 1.8276x; 1.8276x over previous
#include <cuda_runtime.h>
#include <cuda_fp16.h>
#include <cstdint>

#define NN 4096
#define BB 64
#define CC 64
#define EE 16
#define G  4            // batches per block (block N = 256)
#define KC 64           // K per chunk

// ---- arch-specific gate: tcgen05 only in the sm_103a/f pass ----
#if defined(__CUDA_ARCH__) && (__CUDA_ARCH__ == 1030) && \
    (defined(__CUDA_ARCH_SPECIFIC__) || defined(__CUDA_ARCH_FAMILY_SPECIFIC__))
#define USE_TC 1
#else
#define USE_TC 0
#endif

// ---- smem layout (shared by both paths): SW128, 128B rows ----
#define TCA   16384u          // A region: 128 rows * 128B
#define TCB   8192u           // per-batch B region: 64 rows * 128B
#define TCSTG 49152u          // stage: A + 4*B
#define XW_W  65536u          // epi: W region after 4 X tiles (4*16384)
#define SWZ(o) ((o) ^ (((o) >> 3) & 0x70))
#define SMEM_TOTAL 150528
// idesc kind::f16: dtype F32(1<<4), N=64(8<<17), M=128(8<<24)
#define TC_IDESC 0x8100010u

// ---- device buffers (fp16) ----
__device__ __align__(16) __half g_Sh[(size_t)NN * NN];
__device__ __align__(16) __half g_Xh[(size_t)BB * NN * CC];
__device__ __align__(16) __half g_B1T[(size_t)BB * CC * NN];
__device__ __align__(16) __half g_B2T[(size_t)BB * CC * NN];
__device__ __align__(16) __half g_W2T[CC * CC], g_W1T[CC * CC], g_WdT[CC * CC];

__device__ __forceinline__ uint32_t smem_u32(const void* p) {
    uint32_t a;
    asm("{ .reg .u64 t; cvta.to.shared.u64 t, %1; cvt.u32.u64 %0, t; }" : "=r"(a) : "l"(p));
    return a;
}
#define CPA(dst, src) \
    asm volatile("cp.async.cg.shared.global [%0], [%1], 16;" :: "r"(dst), "l"(src) : "memory")
#define CP_COMMIT() asm volatile("cp.async.commit_group;" ::: "memory")
#define CP_WAIT0()  asm volatile("cp.async.wait_group 0;" ::: "memory")
#define CP_WAIT1()  asm volatile("cp.async.wait_group 1;" ::: "memory")

#if USE_TC
// ================= tcgen05 helpers (sm_103a pass only) =================
__device__ __forceinline__ bool elect1() {
    uint32_t r;
    asm volatile("{\n\t.reg .pred p;\n\telect.sync _|p, 0xFFFFFFFF;\n\tselp.b32 %0,1,0,p;\n\t}" : "=r"(r));
    return r != 0;
}
__device__ __forceinline__ uint64_t sdesc(uint32_t addr) {
    // SW128 (layout=2), version=1 (Blackwell), SBO=64, LBO=1
    return 0x4000404000010000ULL | (uint64_t)((addr >> 4) & 0x3FFF);
}
__device__ __forceinline__ void mma_f16_ss(uint32_t d, uint64_t a, uint64_t b, uint32_t en) {
    asm volatile(
        "{\n\t.reg .pred p;\n\tsetp.ne.u32 p, %4, 0;\n\t"
        "tcgen05.mma.cta_group::1.kind::f16 [%0], %1, %2, %3, {%5,%5,%5,%5}, p;\n\t}"
        :: "r"(d), "l"(a), "l"(b), "r"(TC_IDESC), "r"(en), "r"(0u) : "memory");
}
#define TC_COMMIT(mbar) \
    asm volatile("tcgen05.commit.cta_group::1.mbarrier::arrive::one.shared::cluster.b64 [%0];" :: "r"(mbar) : "memory")
#define MBAR_INIT(a) \
    asm volatile("mbarrier.init.shared.b64 [%0], %1;" :: "r"(a), "r"(1u) : "memory")
#define MBAR_INVAL(a) \
    asm volatile("mbarrier.inval.shared.b64 [%0];" :: "r"(a) : "memory")
__device__ __forceinline__ void mbar_wait(uint32_t mbar, uint32_t parity) {
    asm volatile(
        "{\n\t.reg .pred P;\n\tWL_%=:\n\t"
        "mbarrier.try_wait.parity.acquire.cta.shared::cta.b64 P, [%0], %1, 0x989680;\n\t"
        "@P bra.uni WD_%=;\n\tbra.uni WL_%=;\n\tWD_%=:\n\t}"
        :: "r"(mbar), "r"(parity) : "memory");
}
#define TC_ALLOC(sa) \
    asm volatile("tcgen05.alloc.cta_group::1.sync.aligned.shared::cta.b32 [%0], %1;" :: "r"(sa), "r"(256u) : "memory")
#define TC_DEALLOC(tm) \
    asm volatile("tcgen05.dealloc.cta_group::1.sync.aligned.b32 %0, %1;" :: "r"(tm), "r"(256u))
#define TC_FENCE_AFTER()  asm volatile("tcgen05.fence::after_thread_sync;" ::: "memory")
#define TC_WAIT_LD()      asm volatile("tcgen05.wait::ld.sync.aligned;" ::: "memory")
#define FENCE_PROXY()     asm volatile("fence.proxy.async.shared::cta;" ::: "memory")
#define LDTM32(r, a) \
    asm volatile( \
        "tcgen05.ld.sync.aligned.32x32b.x32.b32 " \
        "{%0, %1, %2, %3, %4, %5, %6, %7, " \
        " %8, %9, %10, %11, %12, %13, %14, %15, " \
        " %16, %17, %18, %19, %20, %21, %22, %23, " \
        " %24, %25, %26, %27, %28, %29, %30, %31}, [%32];" \
        : "=r"((r)[0]),  "=r"((r)[1]),  "=r"((r)[2]),  "=r"((r)[3]), \
          "=r"((r)[4]),  "=r"((r)[5]),  "=r"((r)[6]),  "=r"((r)[7]), \
          "=r"((r)[8]),  "=r"((r)[9]),  "=r"((r)[10]), "=r"((r)[11]), \
          "=r"((r)[12]), "=r"((r)[13]), "=r"((r)[14]), "=r"((r)[15]), \
          "=r"((r)[16]), "=r"((r)[17]), "=r"((r)[18]), "=r"((r)[19]), \
          "=r"((r)[20]), "=r"((r)[21]), "=r"((r)[22]), "=r"((r)[23]), \
          "=r"((r)[24]), "=r"((r)[25]), "=r"((r)[26]), "=r"((r)[27]), \
          "=r"((r)[28]), "=r"((r)[29]), "=r"((r)[30]), "=r"((r)[31]) \
        : "r"(a))
#else
// ================= mma.sync helpers (plain sm_103 pass; never executes) ====
__device__ __forceinline__ void ldsm4(uint32_t* r, uint32_t addr) {
    asm volatile("ldmatrix.sync.aligned.m8n8.x4.shared.b16 {%0,%1,%2,%3}, [%4];"
        : "=r"(r[0]), "=r"(r[1]), "=r"(r[2]), "=r"(r[3]) : "r"(addr));
}
__device__ __forceinline__ void mma16816(float* c, const uint32_t* a, const uint32_t* b) {
    asm volatile("mma.sync.aligned.m16n8k16.row.col.f32.f16.f16.f32 "
        "{%0,%1,%2,%3}, {%4,%5,%6,%7}, {%8,%9}, {%0,%1,%2,%3};"
        : "+f"(c[0]), "+f"(c[1]), "+f"(c[2]), "+f"(c[3])
        : "r"(a[0]), "r"(a[1]), "r"(a[2]), "r"(a[3]), "r"(b[0]), "r"(b[1]));
}
#endif

// ---------------------------------------------------------------------------
__global__ __launch_bounds__(256) void supports_kernel(
    const float* __restrict__ adj, const float* __restrict__ emb)
{
    __shared__ float row[NN];
    __shared__ float red[8];
    const int n = blockIdx.x, tid = threadIdx.x;
    const int lane = tid & 31, wid = tid >> 5;

    float a[EE];
#pragma unroll
    for (int e = 0; e < EE; e++) a[e] = adj[n * EE + e];

    float mx = 0.0f;
#pragma unroll
    for (int j = 0; j < NN; j += 256) {
        int m = j + tid;
        float v = 0.0f;
#pragma unroll
        for (int e = 0; e < EE; e++) v = fmaf(a[e], emb[e * NN + m], v);
        v = fmaxf(v, 0.0f);
        row[m] = v;
        mx = fmaxf(mx, v);
    }
#pragma unroll
    for (int o = 16; o > 0; o >>= 1) mx = fmaxf(mx, __shfl_xor_sync(0xffffffffu, mx, o));
    if (lane == 0) red[wid] = mx;
    __syncthreads();
    mx = red[0];
#pragma unroll
    for (int w = 1; w < 8; w++) mx = fmaxf(mx, red[w]);
    __syncthreads();

    float s = 0.0f;
#pragma unroll
    for (int j = 0; j < NN; j += 256) {
        int m = j + tid;
        float e = __expf(row[m] - mx);
        row[m] = e;
        s += e;
    }
#pragma unroll
    for (int o = 16; o > 0; o >>= 1) s += __shfl_xor_sync(0xffffffffu, s, o);
    if (lane == 0) red[wid] = s;
    __syncthreads();
    s = 0.0f;
#pragma unroll
    for (int w = 0; w < 8; w++) s += red[w];
    const float inv = 1.0f / s;
#pragma unroll
    for (int j = 0; j < NN; j += 256) {
        int m = j + tid;
        g_Sh[(size_t)n * NN + m] = __float2half_rn(row[m] * inv);
    }
}

__global__ __launch_bounds__(256) void prep_x(const float* __restrict__ x)
{
    size_t i = (size_t)blockIdx.x * blockDim.x + threadIdx.x;  // float4 index
    float4 v = ((const float4*)x)[i];
    __half2* ph = (__half2*)g_Xh;
    ph[2 * i]     = __half2{__float2half_rn(v.x), __float2half_rn(v.y)};
    ph[2 * i + 1] = __half2{__float2half_rn(v.z), __float2half_rn(v.w)};
}

__global__ void prep_w(const float* __restrict__ W)
{
#pragma unroll
    for (int q = 0; q < 16; q++) {
        int idx = threadIdx.x + q * 256;
        int i = idx >> 6, o = idx & 63;
        int t = o * CC + i;                     // transposed [o][i]
        float w0 = W[i * CC + o];
        float w1 = W[CC * CC + i * CC + o] * 0.5f;
        float w2 = W[2 * CC * CC + i * CC + o];
        g_W2T[t] = __float2half_rn(w2);
        g_W1T[t] = __float2half_rn(w1);
        g_WdT[t] = __float2half_rn(w0 - w2);
    }
}

// ---------------------------------------------------------------------------
// Unified GEMM: D[128 x (4x64)] = sum_k S @ BopT^T (+ X@W epi chunk).
// mode 0: (epi only) B1T = (X@W2)^T;  mode 1: B2T = (2(S@B1)+X@W1)^T;
// mode 2: out = S@B2 + X@(W0-W2) + bias.
// tcgen05 in sm_103a pass (3-stage pipeline, 2 loads in flight);
// simple synchronous mma.sync otherwise (never executes on this bench).
// ---------------------------------------------------------------------------
__global__ __launch_bounds__(256, 1) __cluster_dims__(1, 1, 1)
void cheb_gemm(const float* __restrict__ bias, float* __restrict__ out, int mode)
{
    extern __shared__ char smem[];
    const uint32_t sb = smem_u32(smem);
    const int tid = threadIdx.x, wid = tid >> 5, lane = tid & 31;
    const int b0 = blockIdx.x * G;
    const int n0 = blockIdx.y * 128;

    const __half* Bop = (mode == 1) ? g_B1T : g_B2T;
    const __half* WT  = (mode == 0) ? g_W2T : (mode == 1) ? g_W1T : g_WdT;
    const int nMain = (mode == 0) ? 0 : (NN / KC);

    // 1024-aligned staging base
    const uint32_t st0 = (sb + 32u + 1023u) & ~1023u;
    auto stageA = [&](int s) { return st0 + (uint32_t)s * TCSTG; };

    // ---- shared loaders (identical smem image for both paths) ----
    auto load_main = [&](int cc, uint32_t stA) {
        const int k0 = cc * KC;
#pragma unroll
        for (int q = 0; q < 4; q++) {           // A: 1024 16B ops (S rows)
            int p = tid + 256 * q;
            int r = p >> 3, j = p & 7;
            const __half* s = g_Sh + (size_t)(n0 + r) * NN + k0 + j * 8;
            CPA(stA + SWZ((uint32_t)(r * 128 + j * 16)), s);
        }
#pragma unroll
        for (int q = 0; q < 8; q++) {           // B: 2048 16B ops (4 batches)
            int p = tid + 256 * q;
            int g = p >> 9, rem = p & 511, r = rem >> 3, j = rem & 7;
            const __half* s = Bop + ((size_t)((b0 + g) * CC + r)) * NN + k0 + j * 8;
            CPA(stA + TCA + (uint32_t)g * TCB + SWZ((uint32_t)(r * 128 + j * 16)), s);
        }
    };
    auto load_epi = [&]() {
#pragma unroll
        for (int q = 0; q < 16; q++) {          // X: 4096 ops (4 batches)
            int p = tid + 256 * q;
            int g = p >> 10, r = (p >> 3) & 127, j = p & 7;
            const __half* s = g_Xh + ((size_t)(b0 + g) * NN + n0 + r) * CC + j * 8;
            CPA(st0 + (uint32_t)g * TCA + SWZ((uint32_t)(r * 128 + j * 16)), s);
        }
#pragma unroll
        for (int q = 0; q < 2; q++) {           // W: 512 ops
            int p = tid + 256 * q;
            int r = p >> 3, j = p & 7;
            const __half* s = WT + r * CC + j * 8;
            CPA(st0 + XW_W + SWZ((uint32_t)(r * 128 + j * 16)), s);
        }
    };

#if USE_TC
    // =================== tcgen05 path ===================
    if (wid == 4) TC_ALLOC(sb + 0);
    __syncthreads();
    if (tid == 0) { MBAR_INIT(sb + 8); MBAR_INIT(sb + 16); }
    __syncthreads();
    uint32_t tmem;
    asm volatile("ld.shared.b32 %0, [%1];" : "=r"(tmem) : "r"(sb + 0));

    auto issue_mma = [&](int cc, int first) {
        const uint32_t stA = stageA(cc % 3);
        uint64_t ad = sdesc(stA);
#pragma unroll
        for (int g = 0; g < G; g++) {
            uint64_t bd = sdesc(stA + TCA + (uint32_t)g * TCB);
            uint32_t D = tmem + g * 64;
#pragma unroll
            for (int ks = 0; ks < 4; ks++)
                mma_f16_ss(D, ad + ks * 2, bd + ks * 2, (first && ks == 0) ? 0u : 1u);
        }
        TC_COMMIT(sb + 8 + (uint32_t)(cc & 1) * 8);
    };

    if (nMain > 0) {
        load_main(0, stageA(0)); CP_COMMIT();
        load_main(1, stageA(1)); CP_COMMIT();
        for (int c = 0; c < nMain; c++) {
            if (c + 1 < nMain) CP_WAIT1(); else CP_WAIT0();
            FENCE_PROXY();
            __syncthreads();
            if (wid == 4 && elect1()) issue_mma(c, c == 0);
            if (c + 2 < nMain) {
                // stage (c+2)%3 was last used by MMA c-1 — wait its mbar
                if (c >= 1) mbar_wait(sb + 8 + (uint32_t)((c - 1) & 1) * 8, ((c - 1) >> 1) & 1);
                load_main(c + 2, stageA((c + 2) % 3)); CP_COMMIT();
            }
        }
        // drain last two MMAs before epi overwrites stages
        if (nMain >= 2) mbar_wait(sb + 8 + (uint32_t)((nMain - 2) & 1) * 8, ((nMain - 2) >> 1) & 1);
        mbar_wait(sb + 8 + (uint32_t)((nMain - 1) & 1) * 8, ((nMain - 1) >> 1) & 1);
        __syncthreads();
    }

    // ---- epi chunk: X[b0+g] @ W ----
    load_epi();
    CP_COMMIT(); CP_WAIT0(); FENCE_PROXY();
    __syncthreads();
    if (wid == 4 && elect1()) {
        uint64_t bd = sdesc(st0 + XW_W);
#pragma unroll
        for (int g = 0; g < G; g++) {
            uint64_t ad = sdesc(st0 + (uint32_t)g * TCA);
            uint32_t D = tmem + g * 64;
#pragma unroll
            for (int ks = 0; ks < 4; ks++)
                mma_f16_ss(D, ad + ks * 2, bd + ks * 2, (nMain == 0 && ks == 0) ? 0u : 1u);
        }
        TC_COMMIT(sb + 8 + (uint32_t)(nMain & 1) * 8);
    }
    __syncthreads();
    mbar_wait(sb + 8 + (uint32_t)(nMain & 1) * 8, (nMain >> 1) & 1);
    TC_FENCE_AFTER();

    // ---- epilogue: warps 0-3 read TMEM ----
    if (wid < 4) {
        const int n = n0 + wid * 32 + lane;
#pragma unroll 1
        for (int g = 0; g < G; g++) {
            const int b = b0 + g;
            uint32_t r[64];
            LDTM32(r, tmem + g * 64);
            LDTM32(r + 32, tmem + g * 64 + 32);
            TC_WAIT_LD();
            if (mode == 2) {
#pragma unroll
                for (int cc = 0; cc < 64; cc++)
                    out[((size_t)b * NN + n) * CC + cc] = __uint_as_float(r[cc]) + __ldg(bias + cc);
            } else {
                __half* dh = (mode == 0) ? g_B1T : g_B2T;
                const float sc = (mode == 1) ? 2.0f : 1.0f;
#pragma unroll
                for (int cc = 0; cc < 64; cc++)
                    dh[(size_t)(b * CC + cc) * NN + n] = __float2half_rn(__uint_as_float(r[cc]) * sc);
            }
        }
    }
    __syncthreads();
    if (tid == 0) { MBAR_INVAL(sb + 8); MBAR_INVAL(sb + 16); }
    __syncthreads();
    if (wid == 4) TC_DEALLOC(tmem);

#else
    // ======= mma.sync fallback: synchronous, correct, never executes =======
    const int wm = wid >> 2, wn = wid & 3;     // wm: 0..1 (64 rows), wn: batch
    const int m0 = wm * 64;

    float acc[4][8][4];
#pragma unroll
    for (int a = 0; a < 4; a++)
#pragma unroll
        for (int b = 0; b < 8; b++)
#pragma unroll
            for (int c = 0; c < 4; c++) acc[a][b][c] = 0.0f;

    auto do_chunk = [&](uint32_t aBase, uint32_t bBase) {
#pragma unroll
        for (int kk = 0; kk < 4; kk++) {
            uint32_t A[4][4];
#pragma unroll
            for (int mt = 0; mt < 4; mt++) {
                int row = m0 + mt * 16 + (lane & 15);
                uint32_t off = (uint32_t)row * 128 + kk * 32 + ((lane >> 4) & 1) * 16;
                ldsm4(A[mt], aBase + SWZ(off));
            }
#pragma unroll
            for (int nt = 0; nt < 4; nt++) {
                int row = nt * 16 + (lane & 7) + ((lane >> 4) & 1) * 8;
                uint32_t off = (uint32_t)row * 128 + kk * 32 + ((lane >> 3) & 1) * 16;
                uint32_t Bf[4];
                ldsm4(Bf, bBase + SWZ(off));
#pragma unroll
                for (int mt = 0; mt < 4; mt++) {
                    mma16816(acc[mt][nt * 2 + 0], A[mt], Bf);
                    mma16816(acc[mt][nt * 2 + 1], A[mt], Bf + 2);
                }
            }
        }
    };

    for (int c = 0; c < nMain; c++) {
        load_main(c, stageA(0));
        CP_COMMIT(); CP_WAIT0();
        __syncthreads();
        do_chunk(stageA(0), stageA(0) + TCA + (uint32_t)wn * TCB);
        __syncthreads();
    }
    load_epi();
    CP_COMMIT(); CP_WAIT0();
    __syncthreads();
    do_chunk(st0 + (uint32_t)wn * TCA, st0 + XW_W);

    const int rA = lane >> 2;
    const int c0 = (lane & 3) * 2;
    if (mode == 2) {
#pragma unroll
        for (int mt = 0; mt < 4; mt++) {
            int m = n0 + m0 + mt * 16 + rA;
#pragma unroll
            for (int nt = 0; nt < 8; nt++) {
                int col = nt * 8 + c0;
                float b0v = __ldg(bias + col), b1v = __ldg(bias + col + 1);
                size_t base = ((size_t)(b0 + wn) * NN + m) * CC + col;
                *(float2*)(out + base) = make_float2(acc[mt][nt][0] + b0v, acc[mt][nt][1] + b1v);
                *(float2*)(out + base + 8 * CC) = make_float2(acc[mt][nt][2] + b0v, acc[mt][nt][3] + b1v);
            }
        }
    } else {
        __half* dh = (mode == 0) ? g_B1T : g_B2T;
        const float sc = (mode == 1) ? 2.0f : 1.0f;
#pragma unroll
        for (int mt = 0; mt < 4; mt++) {
            int m = n0 + m0 + mt * 16 + rA;
#pragma unroll
            for (int nt = 0; nt < 8; nt++) {
                int col = nt * 8 + c0;
#pragma unroll
                for (int q = 0; q < 4; q++) {
                    float v = acc[mt][nt][q] * sc;
                    size_t o = ((size_t)((b0 + wn) * CC + col + (q & 1))) * NN + m + (q >> 1) * 8;
                    dh[o] = __float2half_rn(v);
                }
            }
        }
    }
#endif
}

// ---------------------------------------------------------------------------
extern "C" void kernel_launch(void* const* d_in, const int* in_sizes, int n_in,
                              void* d_out, int out_size)
{
    const float* x    = (const float*)d_in[0];  // [64, 4096, 64]
    const float* adj  = (const float*)d_in[1];  // [4096, 16]
    const float* emb  = (const float*)d_in[2];  // [16, 4096]
    const float* W    = (const float*)d_in[3];  // [3, 64, 64]
    const float* bias = (const float*)d_in[4];  // [64]
    float* out = (float*)d_out;                 // [64, 4096, 64]
    (void)in_sizes; (void)n_in; (void)out_size;

    cudaFuncSetAttribute(cheb_gemm, cudaFuncAttributeMaxDynamicSharedMemorySize, SMEM_TOTAL);

    supports_kernel<<<NN, 256>>>(adj, emb);
    prep_x<<<(BB * NN * CC / 4) / 256, 256>>>(x);
    prep_w<<<1, 256>>>(W);

    dim3 grid(BB / G, NN / 128);
    cheb_gemm<<<grid, 256, SMEM_TOTAL>>>(bias, out, 0);  // B1 = X@W2
    cheb_gemm<<<grid, 256, SMEM_TOTAL>>>(bias, out, 1);  // B2 = 2(S@B1) + X@W1
    cheb_gemm<<<grid, 256, SMEM_TOTAL>>>(bias, out, 2);  // out = S@B2 + X@(W0-W2) + bias
}